// round 2
// baseline (speedup 1.0000x reference)
#include <cuda_runtime.h>

#define Bb 8
#define Nn 64
#define Kk 64
#define Tt 128
#define NB1 65
#define KK2 4096
#define NCHUNK 32
#define CHUNKK 128
#define MAXROWS 512

typedef unsigned long long ull;

__device__ __align__(256) float g_chart[NB1 * NB1 * Bb * Kk];
__device__ __align__(256) float g_pair[MAXROWS * KK2];
__device__ __align__(256) float g_part[NCHUNK * MAXROWS * Kk];
__device__ unsigned g_arrive = 0;
__device__ unsigned g_release = 0;

__device__ __forceinline__ int cidx(int i, int j, int b, int k) {
    return ((i * NB1 + j) * Bb + b) * Kk + k;
}
__device__ __forceinline__ ull pack2(float lo, float hi) {
    ull r; asm("mov.b64 %0, {%1, %2};" : "=l"(r) : "f"(lo), "f"(hi)); return r;
}
__device__ __forceinline__ void fma2(ull& d, ull a, ull b) {
    asm("fma.rn.f32x2 %0, %1, %2, %0;" : "+l"(d) : "l"(a), "l"(b));
}
__device__ __forceinline__ float2 unpk(ull v) {
    float2 o; asm("mov.b64 {%0, %1}, %2;" : "=f"(o.x), "=f"(o.y) : "l"(v)); return o;
}

__device__ __forceinline__ void gbar(unsigned target, int nblk) {
    __threadfence();
    __syncthreads();
    if (threadIdx.x == 0) {
        unsigned old = atomicAdd(&g_arrive, 1u);
        if (old == (unsigned)(nblk - 1)) {
            g_arrive = 0;
            __threadfence();
            *(volatile unsigned*)&g_release = target;
        } else {
            while ((int)(*(volatile unsigned*)&g_release - target) < 0) { }
            __threadfence();
        }
    }
    __syncthreads();
}

__global__ void __launch_bounds__(256)
rbn_persistent(const float* __restrict__ seq, const float* __restrict__ rule,
               const float* __restrict__ emit, const float* __restrict__ prior,
               float* __restrict__ out, int nblk)
{
    __shared__ float sA[16 * 72];
    __shared__ float sB[16 * 72];

    const int tid = threadIdx.x;
    const int bid = blockIdx.x;
    const int w = tid >> 5, lane = tid & 31;
    const int tx = tid & 15, ty = tid >> 4;

    unsigned gen = *(volatile unsigned*)&g_release;

    // Phase 0: span-1 cells: chart[i][i+1][b][a] = sum_t emit[a,t]*seq[b,i,t]
    for (int u = bid; u < Nn * Bb; u += nblk) {
        int i = u >> 3, b = u & 7;
        const float* srow = seq + (b * Nn + i) * Tt;
        #pragma unroll
        for (int aa = 0; aa < 8; aa++) {
            int a = w * 8 + aa;
            float p = 0.f;
            #pragma unroll
            for (int q = 0; q < 4; q++) {
                int t2 = lane + q * 32;
                p += emit[a * Tt + t2] * srow[t2];
            }
            #pragma unroll
            for (int off = 16; off; off >>= 1) p += __shfl_down_sync(0xffffffffu, p, off);
            if (lane == 0) g_chart[cidx(i, i + 1, b, a)] = p;
        }
    }
    gbar(++gen, nblk);

    for (int s = 2; s <= Nn; s++) {
        const int m = Nn - s + 1;
        const int rows = m * Bb;

        // Phase A: pair[row][x][y] = sum_{sp=1..s-1} L[x]*R[y]
        for (int u = bid; u < rows; u += nblk) {
            const int cell = u >> 3, b = u & 7;
            const int x0 = ty * 4, y0 = tx * 4;
            ull acc[4][2];
            #pragma unroll
            for (int i = 0; i < 4; i++) { acc[i][0] = 0ull; acc[i][1] = 0ull; }
            const float* Lbase = &g_chart[cidx(cell, cell, b, x0)];
            const float* Rbase = &g_chart[cidx(cell, cell + s, b, y0)];
            #pragma unroll 2
            for (int sp = 1; sp < s; sp++) {
                float4 L = *(const float4*)(Lbase + (size_t)sp * (Bb * Kk));
                float4 R = *(const float4*)(Rbase + (size_t)sp * (NB1 * Bb * Kk));
                ull r01 = pack2(R.x, R.y), r23 = pack2(R.z, R.w);
                ull l;
                l = pack2(L.x, L.x); fma2(acc[0][0], l, r01); fma2(acc[0][1], l, r23);
                l = pack2(L.y, L.y); fma2(acc[1][0], l, r01); fma2(acc[1][1], l, r23);
                l = pack2(L.z, L.z); fma2(acc[2][0], l, r01); fma2(acc[2][1], l, r23);
                l = pack2(L.w, L.w); fma2(acc[3][0], l, r01); fma2(acc[3][1], l, r23);
            }
            #pragma unroll
            for (int i = 0; i < 4; i++) {
                float2 e0 = unpk(acc[i][0]), e1 = unpk(acc[i][1]);
                float4 o; o.x = e0.x; o.y = e0.y; o.z = e1.x; o.w = e1.y;
                *(float4*)&g_pair[(size_t)u * KK2 + (x0 + i) * Kk + y0] = o;
            }
        }
        gbar(++gen, nblk);

        // Phase B: split-K partials: part[chunk][row][a] = pair[row,kc]@ruleT[kc,a]
        const int ntiles = (rows + 63) >> 6;
        const int nunits = ntiles * NCHUNK;
        for (int e = bid; e < nunits; e += nblk) {
            const int tile = e >> 5;
            const int chunk = e & (NCHUNK - 1);
            const int kbase = chunk * CHUNKK;
            ull acc[4][2];
            #pragma unroll
            for (int i = 0; i < 4; i++) { acc[i][0] = 0ull; acc[i][1] = 0ull; }
            const int lr = tid >> 2, lq = tid & 3;
            for (int kb = 0; kb < CHUNKK; kb += 16) {
                float4 va = *(const float4*)&g_pair[(size_t)(tile * 64 + lr) * KK2 + kbase + kb + lq * 4];
                float4 vb = *(const float4*)&rule[(size_t)lr * KK2 + kbase + kb + lq * 4];
                sA[(lq * 4 + 0) * 72 + lr] = va.x;
                sA[(lq * 4 + 1) * 72 + lr] = va.y;
                sA[(lq * 4 + 2) * 72 + lr] = va.z;
                sA[(lq * 4 + 3) * 72 + lr] = va.w;
                sB[(lq * 4 + 0) * 72 + lr] = vb.x;
                sB[(lq * 4 + 1) * 72 + lr] = vb.y;
                sB[(lq * 4 + 2) * 72 + lr] = vb.z;
                sB[(lq * 4 + 3) * 72 + lr] = vb.w;
                __syncthreads();
                #pragma unroll
                for (int k = 0; k < 16; k++) {
                    float4 av = *(const float4*)&sA[k * 72 + ty * 4];
                    float4 bv = *(const float4*)&sB[k * 72 + tx * 4];
                    ull b01 = pack2(bv.x, bv.y), b23 = pack2(bv.z, bv.w);
                    ull a2;
                    a2 = pack2(av.x, av.x); fma2(acc[0][0], a2, b01); fma2(acc[0][1], a2, b23);
                    a2 = pack2(av.y, av.y); fma2(acc[1][0], a2, b01); fma2(acc[1][1], a2, b23);
                    a2 = pack2(av.z, av.z); fma2(acc[2][0], a2, b01); fma2(acc[2][1], a2, b23);
                    a2 = pack2(av.w, av.w); fma2(acc[3][0], a2, b01); fma2(acc[3][1], a2, b23);
                }
                __syncthreads();
            }
            #pragma unroll
            for (int i = 0; i < 4; i++) {
                int row = tile * 64 + ty * 4 + i;
                float2 e0 = unpk(acc[i][0]), e1 = unpk(acc[i][1]);
                float4 o; o.x = e0.x; o.y = e0.y; o.z = e1.x; o.w = e1.y;
                *(float4*)&g_part[(size_t)((chunk << 9) + row) * Kk + tx * 4] = o;
            }
        }
        gbar(++gen, nblk);

        // Phase C: deterministic reduction of 32 partials into chart
        const int total = rows * Kk;
        for (int o = bid * 256 + tid; o < total; o += nblk * 256) {
            const int row = o >> 6, a = o & 63;
            float ssum = 0.f;
            #pragma unroll
            for (int c = 0; c < NCHUNK; c++)
                ssum += g_part[(size_t)((c << 9) + row) * Kk + a];
            const int cell = row >> 3, b = row & 7;
            g_chart[cidx(cell, cell + s, b, a)] = ssum;
        }
        gbar(++gen, nblk);
    }

    // Final: out[b] = sum_a prior[a] * chart[0][N][b][a]
    if (bid == 0 && w < Bb) {
        const int b = w;
        float p = 0.f;
        #pragma unroll
        for (int q = 0; q < 2; q++) {
            int a = lane + q * 32;
            p += prior[a] * g_chart[cidx(0, Nn, b, a)];
        }
        #pragma unroll
        for (int off = 16; off; off >>= 1) p += __shfl_down_sync(0xffffffffu, p, off);
        if (lane == 0) out[b] = p;
    }
}

extern "C" void kernel_launch(void* const* d_in, const int* in_sizes, int n_in,
                              void* d_out, int out_size)
{
    const float* seq   = (const float*)d_in[0];
    const float* rule  = (const float*)d_in[1];
    const float* emit  = (const float*)d_in[2];
    const float* prior = (const float*)d_in[3];
    float* out = (float*)d_out;

    int dev = 0, nsm = 1;
    cudaGetDevice(&dev);
    cudaDeviceGetAttribute(&nsm, cudaDevAttrMultiProcessorCount, dev);
    int bpm = 1;
    cudaOccupancyMaxActiveBlocksPerMultiprocessor(&bpm, rbn_persistent, 256, 0);
    if (bpm < 1) bpm = 1;
    if (bpm > 2) bpm = 2;
    int nblk = nsm * bpm;
    if (nblk > 296) nblk = 296;

    rbn_persistent<<<nblk, 256>>>(seq, rule, emit, prior, out, nblk);
}

// round 3
// speedup vs baseline: 1.3305x; 1.3305x over previous
#include <cuda_runtime.h>

#define Bb 8
#define Nn 64
#define Kk 64
#define Tt 128
#define NB1 65
#define KK2 4096
#define NCHUNK 32
#define CHUNKK 128
#define MAXROWS 512
#define SSTR 76                       // smem row stride (floats), 16B-aligned, low-conflict
#define SMEM_BYTES (CHUNKK * SSTR * 2 * 4)

typedef unsigned long long ull;

__device__ __align__(256) float g_chart[NB1 * NB1 * Bb * Kk];
__device__ __align__(256) float g_pair[MAXROWS * KK2];
__device__ __align__(256) float g_part[NCHUNK * MAXROWS * Kk];

__device__ int g_tile_ready[NB1 * 8];   // [s*8+tile]: A-rows written
__device__ int g_chunk_done[NB1 * 8];   // [s*8+tile]: B-chunks finished
__device__ int g_rows_red[NB1];         // [s]: rows reduced
__device__ int g_cells0;                // phase-0 units done
__device__ volatile int g_level_done;   // highest fully-reduced level
__device__ unsigned g_arrive = 0;
__device__ unsigned g_release = 0;

__device__ __forceinline__ int cidx(int i, int j, int b, int k) {
    return ((i * NB1 + j) * Bb + b) * Kk + k;
}
__device__ __forceinline__ ull pack2(float lo, float hi) {
    ull r; asm("mov.b64 %0, {%1, %2};" : "=l"(r) : "f"(lo), "f"(hi)); return r;
}
__device__ __forceinline__ void fma2(ull& d, ull a, ull b) {
    asm("fma.rn.f32x2 %0, %1, %2, %0;" : "+l"(d) : "l"(a), "l"(b));
}
__device__ __forceinline__ float2 unpk(ull v) {
    float2 o; asm("mov.b64 {%0, %1}, %2;" : "=f"(o.x), "=f"(o.y) : "l"(v)); return o;
}

__device__ __forceinline__ void spin_level(int target) {
    if (threadIdx.x == 0)
        while (g_level_done < target) __nanosleep(32);
    __syncthreads();
}
__device__ __forceinline__ void spin_ctr(int* p, int target) {
    if (threadIdx.x == 0)
        while (__ldcg(p) < target) __nanosleep(32);
    __syncthreads();
}

// single end-of-kernel barrier (generation-counter based, replay-safe)
__device__ __forceinline__ void gbar(unsigned target, int nblk) {
    __threadfence();
    __syncthreads();
    if (threadIdx.x == 0) {
        unsigned old = atomicAdd(&g_arrive, 1u);
        if (old == (unsigned)(nblk - 1)) {
            g_arrive = 0;
            __threadfence();
            *(volatile unsigned*)&g_release = target;
        } else {
            while ((int)(*(volatile unsigned*)&g_release - target) < 0) __nanosleep(32);
            __threadfence();
        }
    }
    __syncthreads();
}

__global__ void __launch_bounds__(256)
rbn_persistent(const float* __restrict__ seq, const float* __restrict__ rule,
               const float* __restrict__ emit, const float* __restrict__ prior,
               float* __restrict__ out, int nblk)
{
    extern __shared__ float smem[];
    float* sA = smem;
    float* sB = smem + CHUNKK * SSTR;

    const int tid = threadIdx.x;
    const int bid = blockIdx.x;
    const int w = tid >> 5, lane = tid & 31;
    const int tx = tid & 15, ty = tid >> 4;

    const unsigned gen = *(volatile unsigned*)&g_release;

    // ---- Phase 0: span-1 cells (no gate needed)
    for (int u = bid; u < Nn * Bb; u += nblk) {
        int i = u >> 3, b = u & 7;
        const float* srow = seq + (b * Nn + i) * Tt;
        #pragma unroll
        for (int aa = 0; aa < 8; aa++) {
            int a = w * 8 + aa;
            float p = 0.f;
            #pragma unroll
            for (int q = 0; q < 4; q++) {
                int t2 = lane + q * 32;
                p += emit[a * Tt + t2] * srow[t2];
            }
            #pragma unroll
            for (int off = 16; off; off >>= 1) p += __shfl_down_sync(0xffffffffu, p, off);
            if (lane == 0) g_chart[cidx(i, i + 1, b, a)] = p;
        }
        __syncthreads();
        if (tid == 0) {
            __threadfence();
            int old = atomicAdd(&g_cells0, 1);
            if (old == Nn * Bb - 1) { __threadfence(); g_level_done = 1; }
        }
    }

    // ---- Levels s = 2..64
    for (int s = 2; s <= Nn; s++) {
        const int m = Nn - s + 1;
        const int rows = m * Bb;
        const int ntiles = (rows + 63) >> 6;
        const int nunits = ntiles * NCHUNK;

        // Phase A: pair[row][x][y] = sum_sp L[x]*R[y]
        if (bid < rows) {
            spin_level(s - 1);
            for (int u = bid; u < rows; u += nblk) {
                const int cell = u >> 3, b = u & 7;
                const int x0 = ty * 4, y0 = tx * 4;
                ull acc[4][2];
                #pragma unroll
                for (int i = 0; i < 4; i++) { acc[i][0] = 0ull; acc[i][1] = 0ull; }
                const float* Lbase = &g_chart[cidx(cell, cell, b, x0)];
                const float* Rbase = &g_chart[cidx(cell, cell + s, b, y0)];
                #pragma unroll 2
                for (int sp = 1; sp < s; sp++) {
                    float4 L = __ldcg((const float4*)(Lbase + (size_t)sp * (Bb * Kk)));
                    float4 R = __ldcg((const float4*)(Rbase + (size_t)sp * (NB1 * Bb * Kk)));
                    ull r01 = pack2(R.x, R.y), r23 = pack2(R.z, R.w);
                    ull l;
                    l = pack2(L.x, L.x); fma2(acc[0][0], l, r01); fma2(acc[0][1], l, r23);
                    l = pack2(L.y, L.y); fma2(acc[1][0], l, r01); fma2(acc[1][1], l, r23);
                    l = pack2(L.z, L.z); fma2(acc[2][0], l, r01); fma2(acc[2][1], l, r23);
                    l = pack2(L.w, L.w); fma2(acc[3][0], l, r01); fma2(acc[3][1], l, r23);
                }
                #pragma unroll
                for (int i = 0; i < 4; i++) {
                    float2 e0 = unpk(acc[i][0]), e1 = unpk(acc[i][1]);
                    float4 o; o.x = e0.x; o.y = e0.y; o.z = e1.x; o.w = e1.y;
                    *(float4*)&g_pair[(size_t)u * KK2 + (x0 + i) * Kk + y0] = o;
                }
                __syncthreads();
                if (tid == 0) {
                    __threadfence();
                    atomicAdd(&g_tile_ready[s * 8 + (u >> 6)], 1);
                }
            }
        }

        // Phase B + fused C: split-K GEMM partials, then cooperative reduction
        for (int e = bid; e < nunits; e += nblk) {
            const int tile = e >> 5;
            const int chunk = e & (NCHUNK - 1);
            const int kbase = chunk * CHUNKK;
            const int R_t = min(64, rows - tile * 64);
            spin_ctr(&g_tile_ready[s * 8 + tile], R_t);

            // stage pair-slice and rule-slice (transposed to [k][row])
            {
                const int lr = tid >> 2, lq = tid & 3;
                const float4* pa = (const float4*)&g_pair[(size_t)(tile * 64 + lr) * KK2 + kbase + lq * 4];
                const float4* pb = (const float4*)&rule[(size_t)lr * KK2 + kbase + lq * 4];
                #pragma unroll
                for (int kb = 0; kb < CHUNKK; kb += 16) {
                    float4 va = __ldcg(pa + (kb >> 2));
                    float4 vb = pb[kb >> 2];
                    int kk = kb + lq * 4;
                    sA[(kk + 0) * SSTR + lr] = va.x;
                    sA[(kk + 1) * SSTR + lr] = va.y;
                    sA[(kk + 2) * SSTR + lr] = va.z;
                    sA[(kk + 3) * SSTR + lr] = va.w;
                    sB[(kk + 0) * SSTR + lr] = vb.x;
                    sB[(kk + 1) * SSTR + lr] = vb.y;
                    sB[(kk + 2) * SSTR + lr] = vb.z;
                    sB[(kk + 3) * SSTR + lr] = vb.w;
                }
            }
            __syncthreads();

            ull acc[4][2];
            #pragma unroll
            for (int i = 0; i < 4; i++) { acc[i][0] = 0ull; acc[i][1] = 0ull; }
            #pragma unroll 4
            for (int k = 0; k < CHUNKK; k++) {
                float4 av = *(const float4*)&sA[k * SSTR + ty * 4];
                float4 bv = *(const float4*)&sB[k * SSTR + tx * 4];
                ull b01 = pack2(bv.x, bv.y), b23 = pack2(bv.z, bv.w);
                ull a2;
                a2 = pack2(av.x, av.x); fma2(acc[0][0], a2, b01); fma2(acc[0][1], a2, b23);
                a2 = pack2(av.y, av.y); fma2(acc[1][0], a2, b01); fma2(acc[1][1], a2, b23);
                a2 = pack2(av.z, av.z); fma2(acc[2][0], a2, b01); fma2(acc[2][1], a2, b23);
                a2 = pack2(av.w, av.w); fma2(acc[3][0], a2, b01); fma2(acc[3][1], a2, b23);
            }
            #pragma unroll
            for (int i = 0; i < 4; i++) {
                int row = tile * 64 + ty * 4 + i;
                float2 e0 = unpk(acc[i][0]), e1 = unpk(acc[i][1]);
                float4 o; o.x = e0.x; o.y = e0.y; o.z = e1.x; o.w = e1.y;
                *(float4*)&g_part[(size_t)((chunk << 9) + row) * Kk + tx * 4] = o;
            }
            __syncthreads();
            if (tid == 0) {
                __threadfence();
                atomicAdd(&g_chunk_done[s * 8 + tile], 1);
            }

            // fused deterministic reduction: each chunk-CTA reduces its 2-row slice
            spin_ctr(&g_chunk_done[s * 8 + tile], NCHUNK);
            const int myr = max(0, min(2, R_t - chunk * 2));
            if (tid < 128) {
                int rl = chunk * 2 + (tid >> 6);
                if (rl < R_t) {
                    int row = tile * 64 + rl, a = tid & 63;
                    float ssum = 0.f;
                    #pragma unroll
                    for (int cc = 0; cc < NCHUNK; cc++)
                        ssum += __ldcg(&g_part[(size_t)((cc << 9) + row) * Kk + a]);
                    int cell = row >> 3, b = row & 7;
                    g_chart[cidx(cell, cell + s, b, a)] = ssum;
                }
            }
            __syncthreads();
            if (tid == 0 && myr > 0) {
                __threadfence();
                int old = atomicAdd(&g_rows_red[s], myr);
                if (old + myr == rows) { __threadfence(); g_level_done = s; }
            }
        }
    }

    // ---- Final: out[b] = sum_a prior[a] * chart[0][N][b][a]
    if (bid == 0) {
        spin_level(Nn);
        if (w < Bb) {
            const int b = w;
            float p = 0.f;
            #pragma unroll
            for (int q = 0; q < 2; q++) {
                int a = lane + q * 32;
                p += prior[a] * __ldcg(&g_chart[cidx(0, Nn, b, a)]);
            }
            #pragma unroll
            for (int off = 16; off; off >>= 1) p += __shfl_down_sync(0xffffffffu, p, off);
            if (lane == 0) out[b] = p;
        }
    }

    // ---- Single end barrier + counter reset for next graph replay
    gbar(gen + 1, nblk);
    if (bid == 0) {
        for (int i = tid; i < NB1 * 8; i += 256) {
            g_tile_ready[i] = 0;
            g_chunk_done[i] = 0;
        }
        for (int i = tid; i < NB1; i += 256) g_rows_red[i] = 0;
        if (tid == 0) { g_cells0 = 0; g_level_done = 0; }
    }
}

extern "C" void kernel_launch(void* const* d_in, const int* in_sizes, int n_in,
                              void* d_out, int out_size)
{
    const float* seq   = (const float*)d_in[0];
    const float* rule  = (const float*)d_in[1];
    const float* emit  = (const float*)d_in[2];
    const float* prior = (const float*)d_in[3];
    float* out = (float*)d_out;

    cudaFuncSetAttribute(rbn_persistent, cudaFuncAttributeMaxDynamicSharedMemorySize, SMEM_BYTES);

    int dev = 0, nsm = 1;
    cudaGetDevice(&dev);
    cudaDeviceGetAttribute(&nsm, cudaDevAttrMultiProcessorCount, dev);
    int bpm = 1;
    cudaOccupancyMaxActiveBlocksPerMultiprocessor(&bpm, rbn_persistent, 256, SMEM_BYTES);
    if (bpm < 1) bpm = 1;
    if (bpm > 2) bpm = 2;
    int nblk = nsm * bpm;
    if (nblk > 296) nblk = 296;
    if (nblk < 32) nblk = 32;   // required for chunk-reduce co-residency (always true on B200)

    rbn_persistent<<<nblk, 256, SMEM_BYTES>>>(seq, rule, emit, prior, out, nblk);
}

// round 4
// speedup vs baseline: 1.3908x; 1.0453x over previous
#include <cuda_runtime.h>

#define Bb 8
#define Nn 64
#define Kk 64
#define Tt 128
#define NB1 65
#define KK2 4096
#define MAXROWS 512
#define SSTR 76
// smem: pairbuf(2*4096 floats) + sA(128*SSTR) + sB(128*SSTR)
#define SMEM_BYTES ((8192 + 2 * 128 * SSTR) * 4)

typedef unsigned long long ull;

__device__ __align__(256) float g_chart[NB1 * NB1 * Bb * Kk];
__device__ __align__(256) float g_pair[MAXROWS * KK2];
__device__ __align__(256) float g_part[32 * MAXROWS * Kk];   // also used as 64 x 256 x 64

__device__ int g_tile_ready[NB1 * 8];
__device__ int g_chunk_done[NB1 * 8];
__device__ int g_rows_red[NB1];
__device__ int g_cells0;
__device__ volatile int g_level_done;
__device__ unsigned g_arrive = 0;
__device__ unsigned g_release = 0;

__device__ __forceinline__ int cidx(int i, int j, int b, int k) {
    return ((i * NB1 + j) * Bb + b) * Kk + k;
}
__device__ __forceinline__ ull pack2(float lo, float hi) {
    ull r; asm("mov.b64 %0, {%1, %2};" : "=l"(r) : "f"(lo), "f"(hi)); return r;
}
__device__ __forceinline__ void fma2(ull& d, ull a, ull b) {
    asm("fma.rn.f32x2 %0, %1, %2, %0;" : "+l"(d) : "l"(a), "l"(b));
}
__device__ __forceinline__ float2 unpk(ull v) {
    float2 o; asm("mov.b64 {%0, %1}, %2;" : "=f"(o.x), "=f"(o.y) : "l"(v)); return o;
}

__device__ __forceinline__ void spin_level(int target) {
    if (threadIdx.x == 0)
        while (g_level_done < target) __nanosleep(20);
    __syncthreads();
}
__device__ __forceinline__ void spin_ctr(int* p, int target) {
    if (threadIdx.x == 0)
        while (__ldcg(p) < target) __nanosleep(20);
    __syncthreads();
}
__device__ __forceinline__ void gbar(unsigned target, int nblk) {
    __threadfence();
    __syncthreads();
    if (threadIdx.x == 0) {
        unsigned old = atomicAdd(&g_arrive, 1u);
        if (old == (unsigned)(nblk - 1)) {
            g_arrive = 0;
            __threadfence();
            *(volatile unsigned*)&g_release = target;
        } else {
            while ((int)(*(volatile unsigned*)&g_release - target) < 0) __nanosleep(20);
            __threadfence();
        }
    }
    __syncthreads();
}

__global__ void __launch_bounds__(256)
rbn_persistent(const float* __restrict__ seq, const float* __restrict__ rule,
               const float* __restrict__ emit, const float* __restrict__ prior,
               float* __restrict__ out, int nblk)
{
    extern __shared__ float smem[];
    float* pairbuf = smem;                 // 2 slots x 4096
    float* sA = smem + 8192;
    float* sB = sA + 128 * SSTR;

    const int tid = threadIdx.x;
    const int bid = blockIdx.x;
    const int w = tid >> 5, lane = tid & 31;
    const int tx = tid & 15, ty = tid >> 4;
    const int x0 = ty * 4, y0 = tx * 4;

    const unsigned gen = *(volatile unsigned*)&g_release;

    // ---- Phase 0: span-1 cells
    for (int u = bid; u < Nn * Bb; u += nblk) {
        int i = u >> 3, b = u & 7;
        const float* srow = seq + (b * Nn + i) * Tt;
        #pragma unroll
        for (int aa = 0; aa < 8; aa++) {
            int a = w * 8 + aa;
            float p = 0.f;
            #pragma unroll
            for (int q = 0; q < 4; q++) {
                int t2 = lane + q * 32;
                p += emit[a * Tt + t2] * srow[t2];
            }
            #pragma unroll
            for (int off = 16; off; off >>= 1) p += __shfl_down_sync(0xffffffffu, p, off);
            if (lane == 0) g_chart[cidx(i, i + 1, b, a)] = p;
        }
        __syncthreads();
        if (tid == 0) {
            __threadfence();
            int old = atomicAdd(&g_cells0, 1);
            if (old == Nn * Bb - 1) { __threadfence(); g_level_done = 1; }
        }
    }

    for (int s = 2; s <= Nn; s++) {
        const int m = Nn - s + 1;
        const int rows = m * Bb;
        const int ntiles = (rows + 63) >> 6;
        const bool modeB = (rows <= 256);
        const int nch = modeB ? 64 : 32;
        const int ck  = modeB ? 64 : 128;
        const int nunits = ntiles * nch;

        // gate level s-1 for everyone (A_final + later A_pre both need it)
        spin_level(s - 1);

        // ---- A_final: pairbuf partial + splits {1, s-1} -> g_pair
        {
            int slot = 0;
            for (int u = bid; u < rows; u += nblk, slot++) {
                const int cell = u >> 3, b = u & 7;
                ull acc[4][2];
                if (s >= 4) {
                    #pragma unroll
                    for (int i = 0; i < 4; i++) {
                        float4 v = *(const float4*)&pairbuf[slot * 4096 + (x0 + i) * 64 + y0];
                        acc[i][0] = pack2(v.x, v.y); acc[i][1] = pack2(v.z, v.w);
                    }
                } else {
                    #pragma unroll
                    for (int i = 0; i < 4; i++) { acc[i][0] = 0ull; acc[i][1] = 0ull; }
                }
                // split sp = 1
                {
                    float4 L = __ldcg((const float4*)&g_chart[cidx(cell, cell + 1, b, x0)]);
                    float4 R = __ldcg((const float4*)&g_chart[cidx(cell + 1, cell + s, b, y0)]);
                    ull r01 = pack2(R.x, R.y), r23 = pack2(R.z, R.w);
                    ull l;
                    l = pack2(L.x, L.x); fma2(acc[0][0], l, r01); fma2(acc[0][1], l, r23);
                    l = pack2(L.y, L.y); fma2(acc[1][0], l, r01); fma2(acc[1][1], l, r23);
                    l = pack2(L.z, L.z); fma2(acc[2][0], l, r01); fma2(acc[2][1], l, r23);
                    l = pack2(L.w, L.w); fma2(acc[3][0], l, r01); fma2(acc[3][1], l, r23);
                }
                // split sp = s-1 (only if s >= 3)
                if (s >= 3) {
                    float4 L = __ldcg((const float4*)&g_chart[cidx(cell, cell + s - 1, b, x0)]);
                    float4 R = __ldcg((const float4*)&g_chart[cidx(cell + s - 1, cell + s, b, y0)]);
                    ull r01 = pack2(R.x, R.y), r23 = pack2(R.z, R.w);
                    ull l;
                    l = pack2(L.x, L.x); fma2(acc[0][0], l, r01); fma2(acc[0][1], l, r23);
                    l = pack2(L.y, L.y); fma2(acc[1][0], l, r01); fma2(acc[1][1], l, r23);
                    l = pack2(L.z, L.z); fma2(acc[2][0], l, r01); fma2(acc[2][1], l, r23);
                    l = pack2(L.w, L.w); fma2(acc[3][0], l, r01); fma2(acc[3][1], l, r23);
                }
                #pragma unroll
                for (int i = 0; i < 4; i++) {
                    float2 e0 = unpk(acc[i][0]), e1 = unpk(acc[i][1]);
                    float4 o; o.x = e0.x; o.y = e0.y; o.z = e1.x; o.w = e1.y;
                    *(float4*)&g_pair[(size_t)u * KK2 + (x0 + i) * Kk + y0] = o;
                }
                __syncthreads();
                if (tid == 0) {
                    __threadfence();
                    atomicAdd(&g_tile_ready[s * 8 + (u >> 6)], 1);
                }
            }
        }

        // ---- B + fused C (exactly <=1 unit per CTA since nunits <= 296)
        for (int e = bid; e < nunits; e += nblk) {
            const int tile  = modeB ? (e >> 6) : (e >> 5);
            const int chunk = modeB ? (e & 63) : (e & 31);
            const int kbase = chunk * ck;
            const int R_t = min(64, rows - tile * 64);
            spin_ctr(&g_tile_ready[s * 8 + tile], R_t);

            {
                const int lr = tid >> 2, lq = tid & 3;
                const float4* pa = (const float4*)&g_pair[(size_t)(tile * 64 + lr) * KK2 + kbase + lq * 4];
                const float4* pb = (const float4*)&rule[(size_t)lr * KK2 + kbase + lq * 4];
                for (int kb = 0; kb < ck; kb += 16) {
                    float4 va = __ldcg(pa + (kb >> 2));
                    float4 vb = pb[kb >> 2];
                    int kk = kb + lq * 4;
                    sA[(kk + 0) * SSTR + lr] = va.x;
                    sA[(kk + 1) * SSTR + lr] = va.y;
                    sA[(kk + 2) * SSTR + lr] = va.z;
                    sA[(kk + 3) * SSTR + lr] = va.w;
                    sB[(kk + 0) * SSTR + lr] = vb.x;
                    sB[(kk + 1) * SSTR + lr] = vb.y;
                    sB[(kk + 2) * SSTR + lr] = vb.z;
                    sB[(kk + 3) * SSTR + lr] = vb.w;
                }
            }
            __syncthreads();

            ull acc[4][2];
            #pragma unroll
            for (int i = 0; i < 4; i++) { acc[i][0] = 0ull; acc[i][1] = 0ull; }
            #pragma unroll 4
            for (int k = 0; k < ck; k++) {
                float4 av = *(const float4*)&sA[k * SSTR + x0];
                float4 bv = *(const float4*)&sB[k * SSTR + y0];
                ull b01 = pack2(bv.x, bv.y), b23 = pack2(bv.z, bv.w);
                ull a2;
                a2 = pack2(av.x, av.x); fma2(acc[0][0], a2, b01); fma2(acc[0][1], a2, b23);
                a2 = pack2(av.y, av.y); fma2(acc[1][0], a2, b01); fma2(acc[1][1], a2, b23);
                a2 = pack2(av.z, av.z); fma2(acc[2][0], a2, b01); fma2(acc[2][1], a2, b23);
                a2 = pack2(av.w, av.w); fma2(acc[3][0], a2, b01); fma2(acc[3][1], a2, b23);
            }
            #pragma unroll
            for (int i = 0; i < 4; i++) {
                int row = tile * 64 + x0 + i;
                int base = modeB ? ((chunk << 8) + row) : ((chunk << 9) + row);
                float2 e0 = unpk(acc[i][0]), e1 = unpk(acc[i][1]);
                float4 o; o.x = e0.x; o.y = e0.y; o.z = e1.x; o.w = e1.y;
                *(float4*)&g_part[(size_t)base * Kk + y0] = o;
            }
            __syncthreads();
            if (tid == 0) {
                __threadfence();
                atomicAdd(&g_chunk_done[s * 8 + tile], 1);
            }

            spin_ctr(&g_chunk_done[s * 8 + tile], nch);
            int myr;
            if (modeB) {
                myr = (chunk < R_t) ? 1 : 0;
                if (tid < 64 && chunk < R_t) {
                    int row = tile * 64 + chunk, a = tid;
                    float ssum = 0.f;
                    #pragma unroll
                    for (int cc = 0; cc < 64; cc++)
                        ssum += __ldcg(&g_part[(size_t)((cc << 8) + row) * Kk + a]);
                    int cell = row >> 3, b = row & 7;
                    g_chart[cidx(cell, cell + s, b, a)] = ssum;
                }
            } else {
                myr = max(0, min(2, R_t - chunk * 2));
                if (tid < 128) {
                    int rl = chunk * 2 + (tid >> 6);
                    if (rl < R_t) {
                        int row = tile * 64 + rl, a = tid & 63;
                        float ssum = 0.f;
                        #pragma unroll
                        for (int cc = 0; cc < 32; cc++)
                            ssum += __ldcg(&g_part[(size_t)((cc << 9) + row) * Kk + a]);
                        int cell = row >> 3, b = row & 7;
                        g_chart[cidx(cell, cell + s, b, a)] = ssum;
                    }
                }
            }
            __syncthreads();
            if (tid == 0 && myr > 0) {
                __threadfence();
                int old = atomicAdd(&g_rows_red[s], myr);
                if (old + myr == rows) { __threadfence(); g_level_done = s; }
            }
        }

        // ---- A_pre(s+1): splits 2..s-1 (levels <= s-1, already gated) -> pairbuf
        if (s < Nn) {
            const int s2 = s + 1;
            if (s2 >= 4) {
                const int rows2 = (Nn - s2 + 1) * Bb;
                int slot = 0;
                for (int u = bid; u < rows2; u += nblk, slot++) {
                    const int cell = u >> 3, b = u & 7;
                    ull acc[4][2];
                    #pragma unroll
                    for (int i = 0; i < 4; i++) { acc[i][0] = 0ull; acc[i][1] = 0ull; }
                    const float* Lbase = &g_chart[cidx(cell, cell, b, x0)];
                    const float* Rbase = &g_chart[cidx(cell, cell + s2, b, y0)];
                    #pragma unroll 4
                    for (int sp = 2; sp <= s2 - 2; sp++) {
                        float4 L = __ldcg((const float4*)(Lbase + (size_t)sp * (Bb * Kk)));
                        float4 R = __ldcg((const float4*)(Rbase + (size_t)sp * (NB1 * Bb * Kk)));
                        ull r01 = pack2(R.x, R.y), r23 = pack2(R.z, R.w);
                        ull l;
                        l = pack2(L.x, L.x); fma2(acc[0][0], l, r01); fma2(acc[0][1], l, r23);
                        l = pack2(L.y, L.y); fma2(acc[1][0], l, r01); fma2(acc[1][1], l, r23);
                        l = pack2(L.z, L.z); fma2(acc[2][0], l, r01); fma2(acc[2][1], l, r23);
                        l = pack2(L.w, L.w); fma2(acc[3][0], l, r01); fma2(acc[3][1], l, r23);
                    }
                    #pragma unroll
                    for (int i = 0; i < 4; i++) {
                        float2 e0 = unpk(acc[i][0]), e1 = unpk(acc[i][1]);
                        float4 o; o.x = e0.x; o.y = e0.y; o.z = e1.x; o.w = e1.y;
                        *(float4*)&pairbuf[slot * 4096 + (x0 + i) * 64 + y0] = o;
                    }
                }
                __syncthreads();
            }
        }
    }

    // ---- Final output
    if (bid == 0) {
        spin_level(Nn);
        if (w < Bb) {
            const int b = w;
            float p = 0.f;
            #pragma unroll
            for (int q = 0; q < 2; q++) {
                int a = lane + q * 32;
                p += prior[a] * __ldcg(&g_chart[cidx(0, Nn, b, a)]);
            }
            #pragma unroll
            for (int off = 16; off; off >>= 1) p += __shfl_down_sync(0xffffffffu, p, off);
            if (lane == 0) out[b] = p;
        }
    }

    // ---- End barrier + reset for next replay
    gbar(gen + 1, nblk);
    if (bid == 0) {
        for (int i = tid; i < NB1 * 8; i += 256) {
            g_tile_ready[i] = 0;
            g_chunk_done[i] = 0;
        }
        for (int i = tid; i < NB1; i += 256) g_rows_red[i] = 0;
        if (tid == 0) { g_cells0 = 0; g_level_done = 0; }
    }
}

extern "C" void kernel_launch(void* const* d_in, const int* in_sizes, int n_in,
                              void* d_out, int out_size)
{
    const float* seq   = (const float*)d_in[0];
    const float* rule  = (const float*)d_in[1];
    const float* emit  = (const float*)d_in[2];
    const float* prior = (const float*)d_in[3];
    float* out = (float*)d_out;

    cudaFuncSetAttribute(rbn_persistent, cudaFuncAttributeMaxDynamicSharedMemorySize, SMEM_BYTES);

    int dev = 0, nsm = 1;
    cudaGetDevice(&dev);
    cudaDeviceGetAttribute(&nsm, cudaDevAttrMultiProcessorCount, dev);
    int bpm = 1;
    cudaOccupancyMaxActiveBlocksPerMultiprocessor(&bpm, rbn_persistent, 256, SMEM_BYTES);
    if (bpm < 1) bpm = 1;
    if (bpm > 2) bpm = 2;
    int nblk = nsm * bpm;
    if (nblk > 296) nblk = 296;
    if (nblk < 64) nblk = 64;

    rbn_persistent<<<nblk, 256, SMEM_BYTES>>>(seq, rule, emit, prior, out, nblk);
}

// round 5
// speedup vs baseline: 1.5346x; 1.1034x over previous
#include <cuda_runtime.h>

#define Bb 8
#define Nn 64
#define Kk 64
#define Tt 128
#define NB1 65
#define KK2 4096
#define MAXROWS 512
#define SSTR 68
#define SMEM_BYTES (2 * 128 * SSTR * 4)   // 69632 bytes -> 3 CTAs/SM
#define CSTR 32                           // counter stride (ints) = 128B

typedef unsigned long long ull;

__device__ __align__(256) float g_chart[NB1 * NB1 * Bb * Kk];
__device__ __align__(256) float g_pair2[2][MAXROWS * KK2];
__device__ __align__(256) float g_part[32 * MAXROWS * Kk];

__device__ int g_tile_ready[NB1 * 8 * CSTR];
__device__ int g_chunk_done[NB1 * 8 * CSTR];
__device__ int g_red_tile [NB1 * 8 * CSTR];
__device__ int g_tiles_done[NB1 * CSTR];
__device__ int g_cells0;
__device__ int g_level_done;
__device__ unsigned g_arrive = 0;
__device__ unsigned g_release = 0;

__device__ __forceinline__ int cidx(int i, int j, int b, int k) {
    return ((i * NB1 + j) * Bb + b) * Kk + k;
}
__device__ __forceinline__ ull pack2(float lo, float hi) {
    ull r; asm("mov.b64 %0, {%1, %2};" : "=l"(r) : "f"(lo), "f"(hi)); return r;
}
__device__ __forceinline__ void fma2(ull& d, ull a, ull b) {
    asm("fma.rn.f32x2 %0, %1, %2, %0;" : "+l"(d) : "l"(a), "l"(b));
}
__device__ __forceinline__ float2 unpk(ull v) {
    float2 o; asm("mov.b64 {%0, %1}, %2;" : "=f"(o.x), "=f"(o.y) : "l"(v)); return o;
}
__device__ __forceinline__ int ld_acq(const int* p) {
    int v; asm volatile("ld.acquire.gpu.global.b32 %0, [%1];" : "=r"(v) : "l"(p) : "memory"); return v;
}
__device__ __forceinline__ void red_rel(int* p, int v) {
    asm volatile("red.release.gpu.global.add.s32 [%0], %1;" :: "l"(p), "r"(v) : "memory");
}
__device__ __forceinline__ int atom_rel(int* p, int v) {
    int o; asm volatile("atom.release.gpu.global.add.s32 %0, [%1], %2;" : "=r"(o) : "l"(p), "r"(v) : "memory"); return o;
}
__device__ __forceinline__ void st_rel(int* p, int v) {
    asm volatile("st.release.gpu.global.b32 [%0], %1;" :: "l"(p), "r"(v) : "memory");
}

__device__ __forceinline__ void spin_ctr(int* p, int target) {
    if (threadIdx.x == 0) {
        int it = 0;
        while (ld_acq(p) < target) { __nanosleep(it < 8 ? 32 : 128); it++; }
    }
    __syncthreads();
}
__device__ __forceinline__ void spin_level(int target) {
    if (threadIdx.x == 0) {
        int it = 0;
        while (ld_acq(&g_level_done) < target) { __nanosleep(it < 8 ? 32 : 128); it++; }
    }
    __syncthreads();
}
__device__ __forceinline__ void gbar(unsigned target, int nblk) {
    __threadfence();
    __syncthreads();
    if (threadIdx.x == 0) {
        unsigned old = atomicAdd(&g_arrive, 1u);
        if (old == (unsigned)(nblk - 1)) {
            g_arrive = 0;
            __threadfence();
            *(volatile unsigned*)&g_release = target;
        } else {
            while ((int)(*(volatile unsigned*)&g_release - target) < 0) __nanosleep(64);
            __threadfence();
        }
    }
    __syncthreads();
}

__global__ void __launch_bounds__(256, 3)
rbn_persistent(const float* __restrict__ seq, const float* __restrict__ rule,
               const float* __restrict__ emit, const float* __restrict__ prior,
               float* __restrict__ out, int nblk)
{
    extern __shared__ float smem[];
    float* sA = smem;
    float* sB = smem + 128 * SSTR;

    const int tid = threadIdx.x;
    const int bid = blockIdx.x;
    const int w = tid >> 5, lane = tid & 31;
    const int tx = tid & 15, ty = tid >> 4;
    const int x0 = ty * 4, y0 = tx * 4;

    const unsigned gen = *(volatile unsigned*)&g_release;

    // ---- Phase 0: span-1 cells
    for (int u = bid; u < Nn * Bb; u += nblk) {
        int i = u >> 3, b = u & 7;
        const float* srow = seq + (b * Nn + i) * Tt;
        #pragma unroll
        for (int aa = 0; aa < 8; aa++) {
            int a = w * 8 + aa;
            float p = 0.f;
            #pragma unroll
            for (int q = 0; q < 4; q++) {
                int t2 = lane + q * 32;
                p += emit[a * Tt + t2] * srow[t2];
            }
            #pragma unroll
            for (int off = 16; off; off >>= 1) p += __shfl_down_sync(0xffffffffu, p, off);
            if (lane == 0) g_chart[cidx(i, i + 1, b, a)] = p;
        }
        __threadfence();
        __syncthreads();
        if (tid == 0) {
            int old = atom_rel(&g_cells0, 1);
            if (old == Nn * Bb - 1) st_rel(&g_level_done, 1);
        }
    }

    for (int s = 2; s <= Nn; s++) {
        const int m = Nn - s + 1;
        const int rows = m * Bb;
        const int ntiles = (rows + 63) >> 6;
        const bool modeB = (rows <= 256);
        const int nch = modeB ? 64 : 32;
        const int ck  = modeB ? 64 : 128;
        const int nunits = ntiles * nch;
        float* const pairc = g_pair2[s & 1];

        // ---- A_final (only CTAs with rows; gated on level s-1)
        if (bid < rows) {
            spin_level(s - 1);
            for (int u = bid; u < rows; u += nblk) {
                const int cell = u >> 3, b = u & 7;
                ull acc[4][2];
                if (s >= 4) {
                    #pragma unroll
                    for (int i = 0; i < 4; i++) {
                        float4 v = __ldcg((const float4*)&pairc[(size_t)u * KK2 + (x0 + i) * Kk + y0]);
                        acc[i][0] = pack2(v.x, v.y); acc[i][1] = pack2(v.z, v.w);
                    }
                } else {
                    #pragma unroll
                    for (int i = 0; i < 4; i++) { acc[i][0] = 0ull; acc[i][1] = 0ull; }
                }
                {
                    float4 L = __ldcg((const float4*)&g_chart[cidx(cell, cell + 1, b, x0)]);
                    float4 R = __ldcg((const float4*)&g_chart[cidx(cell + 1, cell + s, b, y0)]);
                    ull r01 = pack2(R.x, R.y), r23 = pack2(R.z, R.w);
                    ull l;
                    l = pack2(L.x, L.x); fma2(acc[0][0], l, r01); fma2(acc[0][1], l, r23);
                    l = pack2(L.y, L.y); fma2(acc[1][0], l, r01); fma2(acc[1][1], l, r23);
                    l = pack2(L.z, L.z); fma2(acc[2][0], l, r01); fma2(acc[2][1], l, r23);
                    l = pack2(L.w, L.w); fma2(acc[3][0], l, r01); fma2(acc[3][1], l, r23);
                }
                if (s >= 3) {
                    float4 L = __ldcg((const float4*)&g_chart[cidx(cell, cell + s - 1, b, x0)]);
                    float4 R = __ldcg((const float4*)&g_chart[cidx(cell + s - 1, cell + s, b, y0)]);
                    ull r01 = pack2(R.x, R.y), r23 = pack2(R.z, R.w);
                    ull l;
                    l = pack2(L.x, L.x); fma2(acc[0][0], l, r01); fma2(acc[0][1], l, r23);
                    l = pack2(L.y, L.y); fma2(acc[1][0], l, r01); fma2(acc[1][1], l, r23);
                    l = pack2(L.z, L.z); fma2(acc[2][0], l, r01); fma2(acc[2][1], l, r23);
                    l = pack2(L.w, L.w); fma2(acc[3][0], l, r01); fma2(acc[3][1], l, r23);
                }
                #pragma unroll
                for (int i = 0; i < 4; i++) {
                    float2 e0 = unpk(acc[i][0]), e1 = unpk(acc[i][1]);
                    float4 o; o.x = e0.x; o.y = e0.y; o.z = e1.x; o.w = e1.y;
                    *(float4*)&pairc[(size_t)u * KK2 + (x0 + i) * Kk + y0] = o;
                }
                __threadfence();
                __syncthreads();
                if (tid == 0) red_rel(&g_tile_ready[(s * 8 + (u >> 6)) * CSTR], 1);
            }
        }

        // ---- B + fused C: one unit per CTA (nunits <= 256 <= nblk)
        if (bid < nunits) {
            const int tile  = modeB ? (bid >> 6) : (bid >> 5);
            const int chunk = modeB ? (bid & 63) : (bid & 31);
            const int kbase = chunk * ck;
            const int R_t = min(64, rows - tile * 64);
            const int lr = tid >> 2, lq = tid & 3;

            // prefetch rule slice into sB BEFORE waiting
            {
                const float4* pb = (const float4*)&rule[(size_t)lr * KK2 + kbase + lq * 4];
                for (int kb = 0; kb < ck; kb += 16) {
                    float4 vb = pb[kb >> 2];
                    int kk = kb + lq * 4;
                    sB[(kk + 0) * SSTR + lr] = vb.x;
                    sB[(kk + 1) * SSTR + lr] = vb.y;
                    sB[(kk + 2) * SSTR + lr] = vb.z;
                    sB[(kk + 3) * SSTR + lr] = vb.w;
                }
            }
            spin_ctr(&g_tile_ready[(s * 8 + tile) * CSTR], R_t);
            {
                const float4* pa = (const float4*)&pairc[(size_t)(tile * 64 + lr) * KK2 + kbase + lq * 4];
                for (int kb = 0; kb < ck; kb += 16) {
                    float4 va = __ldcg(pa + (kb >> 2));
                    int kk = kb + lq * 4;
                    sA[(kk + 0) * SSTR + lr] = va.x;
                    sA[(kk + 1) * SSTR + lr] = va.y;
                    sA[(kk + 2) * SSTR + lr] = va.z;
                    sA[(kk + 3) * SSTR + lr] = va.w;
                }
            }
            __syncthreads();

            ull acc[4][2];
            #pragma unroll
            for (int i = 0; i < 4; i++) { acc[i][0] = 0ull; acc[i][1] = 0ull; }
            #pragma unroll 8
            for (int k = 0; k < ck; k++) {
                float4 av = *(const float4*)&sA[k * SSTR + x0];
                float4 bv = *(const float4*)&sB[k * SSTR + y0];
                ull b01 = pack2(bv.x, bv.y), b23 = pack2(bv.z, bv.w);
                ull a2;
                a2 = pack2(av.x, av.x); fma2(acc[0][0], a2, b01); fma2(acc[0][1], a2, b23);
                a2 = pack2(av.y, av.y); fma2(acc[1][0], a2, b01); fma2(acc[1][1], a2, b23);
                a2 = pack2(av.z, av.z); fma2(acc[2][0], a2, b01); fma2(acc[2][1], a2, b23);
                a2 = pack2(av.w, av.w); fma2(acc[3][0], a2, b01); fma2(acc[3][1], a2, b23);
            }
            #pragma unroll
            for (int i = 0; i < 4; i++) {
                int row = tile * 64 + x0 + i;
                int base = modeB ? ((chunk << 8) + row) : ((chunk << 9) + row);
                float2 e0 = unpk(acc[i][0]), e1 = unpk(acc[i][1]);
                float4 o; o.x = e0.x; o.y = e0.y; o.z = e1.x; o.w = e1.y;
                *(float4*)&g_part[(size_t)base * Kk + y0] = o;
            }
            __threadfence();
            __syncthreads();
            if (tid == 0) red_rel(&g_chunk_done[(s * 8 + tile) * CSTR], 1);

            spin_ctr(&g_chunk_done[(s * 8 + tile) * CSTR], nch);
            if (modeB) {
                if (tid < 64 && chunk < R_t) {
                    int row = tile * 64 + chunk, a = tid;
                    float ssum = 0.f;
                    #pragma unroll 16
                    for (int cc = 0; cc < 64; cc++)
                        ssum += __ldcg(&g_part[(size_t)((cc << 8) + row) * Kk + a]);
                    int cell = row >> 3, b = row & 7;
                    g_chart[cidx(cell, cell + s, b, a)] = ssum;
                }
            } else {
                if (tid < 128) {
                    int rl = chunk * 2 + (tid >> 6);
                    if (rl < R_t) {
                        int row = tile * 64 + rl, a = tid & 63;
                        float ssum = 0.f;
                        #pragma unroll 16
                        for (int cc = 0; cc < 32; cc++)
                            ssum += __ldcg(&g_part[(size_t)((cc << 9) + row) * Kk + a]);
                        int cell = row >> 3, b = row & 7;
                        g_chart[cidx(cell, cell + s, b, a)] = ssum;
                    }
                }
            }
            __threadfence();
            __syncthreads();
            if (tid == 0) {
                int old = atom_rel(&g_red_tile[(s * 8 + tile) * CSTR], 1);
                if (old == nch - 1) {
                    int t = atom_rel(&g_tiles_done[s * CSTR], 1);
                    if (t == ntiles - 1) st_rel(&g_level_done, s);
                }
            }
        }

        // ---- A_pre(s+1): splits 2..s-1 -> g_pair2[(s+1)&1]
        if (s < Nn && s + 1 >= 4) {
            const int s2 = s + 1;
            const int rows2 = (Nn - s2 + 1) * Bb;
            float* const pairn = g_pair2[s2 & 1];
            for (int u = bid; u < rows2; u += nblk) {
                const int cell = u >> 3, b = u & 7;
                ull acc[4][2];
                #pragma unroll
                for (int i = 0; i < 4; i++) { acc[i][0] = 0ull; acc[i][1] = 0ull; }
                const float* Lbase = &g_chart[cidx(cell, cell, b, x0)];
                const float* Rbase = &g_chart[cidx(cell, cell + s2, b, y0)];
                #pragma unroll 4
                for (int sp = 2; sp <= s2 - 2; sp++) {
                    float4 L = __ldcg((const float4*)(Lbase + (size_t)sp * (Bb * Kk)));
                    float4 R = __ldcg((const float4*)(Rbase + (size_t)sp * (NB1 * Bb * Kk)));
                    ull r01 = pack2(R.x, R.y), r23 = pack2(R.z, R.w);
                    ull l;
                    l = pack2(L.x, L.x); fma2(acc[0][0], l, r01); fma2(acc[0][1], l, r23);
                    l = pack2(L.y, L.y); fma2(acc[1][0], l, r01); fma2(acc[1][1], l, r23);
                    l = pack2(L.z, L.z); fma2(acc[2][0], l, r01); fma2(acc[2][1], l, r23);
                    l = pack2(L.w, L.w); fma2(acc[3][0], l, r01); fma2(acc[3][1], l, r23);
                }
                #pragma unroll
                for (int i = 0; i < 4; i++) {
                    float2 e0 = unpk(acc[i][0]), e1 = unpk(acc[i][1]);
                    float4 o; o.x = e0.x; o.y = e0.y; o.z = e1.x; o.w = e1.y;
                    *(float4*)&pairn[(size_t)u * KK2 + (x0 + i) * Kk + y0] = o;
                }
            }
        }
    }

    // ---- Final output
    if (bid == 0) {
        spin_level(Nn);
        if (w < Bb) {
            const int b = w;
            float p = 0.f;
            #pragma unroll
            for (int q = 0; q < 2; q++) {
                int a = lane + q * 32;
                p += prior[a] * __ldcg(&g_chart[cidx(0, Nn, b, a)]);
            }
            #pragma unroll
            for (int off = 16; off; off >>= 1) p += __shfl_down_sync(0xffffffffu, p, off);
            if (lane == 0) out[b] = p;
        }
    }

    // ---- End barrier + counter reset for next replay
    gbar(gen + 1, nblk);
    if (bid == 0) {
        for (int i = tid; i < NB1 * 8 * CSTR; i += 256) {
            g_tile_ready[i] = 0;
            g_chunk_done[i] = 0;
            g_red_tile[i] = 0;
        }
        for (int i = tid; i < NB1 * CSTR; i += 256) g_tiles_done[i] = 0;
        if (tid == 0) { g_cells0 = 0; g_level_done = 0; }
    }
}

extern "C" void kernel_launch(void* const* d_in, const int* in_sizes, int n_in,
                              void* d_out, int out_size)
{
    const float* seq   = (const float*)d_in[0];
    const float* rule  = (const float*)d_in[1];
    const float* emit  = (const float*)d_in[2];
    const float* prior = (const float*)d_in[3];
    float* out = (float*)d_out;

    cudaFuncSetAttribute(rbn_persistent, cudaFuncAttributeMaxDynamicSharedMemorySize, SMEM_BYTES);

    int dev = 0, nsm = 1;
    cudaGetDevice(&dev);
    cudaDeviceGetAttribute(&nsm, cudaDevAttrMultiProcessorCount, dev);
    int bpm = 1;
    cudaOccupancyMaxActiveBlocksPerMultiprocessor(&bpm, rbn_persistent, 256, SMEM_BYTES);
    if (bpm < 1) bpm = 1;
    if (bpm > 3) bpm = 3;
    int nblk = nsm * bpm;
    if (nblk > 444) nblk = 444;
    if (nblk < 256) nblk = 256;   // co-residency floor for the 256 B units (3 CTAs/SM holds on B200)

    rbn_persistent<<<nblk, 256, SMEM_BYTES>>>(seq, rule, emit, prior, out, nblk);
}

// round 6
// speedup vs baseline: 1.5876x; 1.0345x over previous
#include <cuda_runtime.h>

#define Bb 8
#define Nn 64
#define Kk 64
#define Tt 128
#define NB1 65
#define KK2 4096
#define MAXROWS 512
#define SSTR 68
#define SMEM_BYTES (2 * 128 * SSTR * 4)   // 69632 -> 3 CTAs/SM
#define CSTR 32

typedef unsigned long long ull;

__device__ __align__(256) float g_chart[NB1 * NB1 * Bb * Kk];
__device__ __align__(256) float g_pair2[2][MAXROWS * KK2];
__device__ __align__(256) float g_part[32 * MAXROWS * Kk];

__device__ int g_pre_ready[NB1 * 8 * CSTR];
__device__ int g_chunk_done[NB1 * 8 * CSTR];
__device__ int g_red_tile [NB1 * 8 * CSTR];
__device__ int g_tiles_done[NB1 * CSTR];
__device__ int g_cells0;
__device__ int g_level_done;
__device__ unsigned g_arrive = 0;
__device__ unsigned g_release = 0;

__device__ __forceinline__ int cidx(int i, int j, int b, int k) {
    return ((i * NB1 + j) * Bb + b) * Kk + k;
}
__device__ __forceinline__ ull pack2(float lo, float hi) {
    ull r; asm("mov.b64 %0, {%1, %2};" : "=l"(r) : "f"(lo), "f"(hi)); return r;
}
__device__ __forceinline__ void fma2(ull& d, ull a, ull b) {
    asm("fma.rn.f32x2 %0, %1, %2, %0;" : "+l"(d) : "l"(a), "l"(b));
}
__device__ __forceinline__ float2 unpk(ull v) {
    float2 o; asm("mov.b64 {%0, %1}, %2;" : "=f"(o.x), "=f"(o.y) : "l"(v)); return o;
}
__device__ __forceinline__ int ld_acq(const int* p) {
    int v; asm volatile("ld.acquire.gpu.global.b32 %0, [%1];" : "=r"(v) : "l"(p) : "memory"); return v;
}
__device__ __forceinline__ void red_rel(int* p, int v) {
    asm volatile("red.release.gpu.global.add.s32 [%0], %1;" :: "l"(p), "r"(v) : "memory");
}
__device__ __forceinline__ int atom_ar(int* p, int v) {
    int o; asm volatile("atom.acq_rel.gpu.global.add.s32 %0, [%1], %2;" : "=r"(o) : "l"(p), "r"(v) : "memory"); return o;
}
__device__ __forceinline__ void st_rel(int* p, int v) {
    asm volatile("st.release.gpu.global.b32 [%0], %1;" :: "l"(p), "r"(v) : "memory");
}

__device__ __forceinline__ void spin_ctr(int* p, int target) {
    if (threadIdx.x == 0) {
        while (ld_acq(p) < target) { }
    }
    __syncthreads();
}
__device__ __forceinline__ void spin_level(int target) {
    if (threadIdx.x == 0) {
        while (ld_acq(&g_level_done) < target) { }
    }
    __syncthreads();
}
__device__ __forceinline__ void gbar(unsigned target, int nblk) {
    __threadfence();
    __syncthreads();
    if (threadIdx.x == 0) {
        unsigned old = atomicAdd(&g_arrive, 1u);
        if (old == (unsigned)(nblk - 1)) {
            g_arrive = 0;
            __threadfence();
            *(volatile unsigned*)&g_release = target;
        } else {
            while ((int)(*(volatile unsigned*)&g_release - target) < 0) __nanosleep(64);
            __threadfence();
        }
    }
    __syncthreads();
}

__global__ void __launch_bounds__(256, 3)
rbn_persistent(const float* __restrict__ seq, const float* __restrict__ rule,
               const float* __restrict__ emit, const float* __restrict__ prior,
               float* __restrict__ out, int nblk)
{
    extern __shared__ float smem[];
    float* sA = smem;
    float* sB = smem + 128 * SSTR;

    const int tid = threadIdx.x;
    const int bid = blockIdx.x;
    const int w = tid >> 5, lane = tid & 31;
    const int tx = tid & 15, ty = tid >> 4;
    const int x0 = ty * 4, y0r = tx * 4;

    const unsigned gen = *(volatile unsigned*)&g_release;

    // ---- Phase 0: span-1 cells
    for (int u = bid; u < Nn * Bb; u += nblk) {
        int i = u >> 3, b = u & 7;
        const float* srow = seq + (b * Nn + i) * Tt;
        #pragma unroll
        for (int aa = 0; aa < 8; aa++) {
            int a = w * 8 + aa;
            float p = 0.f;
            #pragma unroll
            for (int q = 0; q < 4; q++) {
                int t2 = lane + q * 32;
                p += emit[a * Tt + t2] * srow[t2];
            }
            #pragma unroll
            for (int off = 16; off; off >>= 1) p += __shfl_down_sync(0xffffffffu, p, off);
            if (lane == 0) g_chart[cidx(i, i + 1, b, a)] = p;
        }
        __syncthreads();
        if (tid == 0) {
            int old = atom_ar(&g_cells0, 1);
            if (old == Nn * Bb - 1) st_rel(&g_level_done, 1);
        }
    }

    for (int s = 2; s <= Nn; s++) {
        const int m = Nn - s + 1;
        const int rows = m * Bb;
        const int ntiles = (rows + 63) >> 6;
        const bool modeB = (rows <= 256);
        const int nch = modeB ? 64 : 32;
        const int ck  = modeB ? 64 : 128;
        const int nunits = ntiles * nch;
        float* const pairc = g_pair2[s & 1];

        int tile = 0, chunk = 0, kbase = 0, R_t = 0;
        const int lr = tid >> 2, lq = tid & 3;
        if (bid < nunits) {
            tile  = modeB ? (bid >> 6) : (bid >> 5);
            chunk = modeB ? (bid & 63) : (bid & 31);
            kbase = chunk * ck;
            R_t = min(64, rows - tile * 64);
            // prefetch rule slice (constant data) before any gate
            const float4* pb = (const float4*)&rule[(size_t)lr * KK2 + kbase + lq * 4];
            for (int kb = 0; kb < ck; kb += 16) {
                float4 vb = pb[kb >> 2];
                int kk = kb + lq * 4;
                sB[(kk + 0) * SSTR + lr] = vb.x;
                sB[(kk + 1) * SSTR + lr] = vb.y;
                sB[(kk + 2) * SSTR + lr] = vb.z;
                sB[(kk + 3) * SSTR + lr] = vb.w;
            }
        }

        spin_level(s - 1);       // all CTAs: gates B's chart reads AND A_pre below

        if (bid < nunits) {
            if (s >= 4) spin_ctr(&g_pre_ready[(s * 8 + tile) * CSTR], R_t);

            // ---- stage sA = pairc + split{1} + split{s-1} contributions (fused A_final)
            {
                const int row = tile * 64 + lr;
                const int cell = row >> 3, b = row & 7;
                const float* L1row = &g_chart[cidx(cell, cell + 1, b, 0)];
                const float* R1row = &g_chart[cidx(cell + 1, cell + s, b, 0)];
                const float* L2row = &g_chart[cidx(cell, cell + s - 1, b, 0)];
                const float* R2row = &g_chart[cidx(cell + s - 1, cell + s, b, 0)];
                const float4* pa = (const float4*)&pairc[(size_t)row * KK2 + kbase + lq * 4];
                for (int kb = 0; kb < ck; kb += 16) {
                    const int kk = kb + lq * 4;
                    const int kg = kbase + kk;
                    const int xx = kg >> 6, yy = kg & 63;
                    float4 va;
                    if (s >= 4) va = __ldcg(pa + (kb >> 2));
                    else { va.x = 0.f; va.y = 0.f; va.z = 0.f; va.w = 0.f; }
                    {
                        float l1 = __ldcg(L1row + xx);
                        float4 r1 = __ldcg((const float4*)(R1row + yy));
                        va.x += l1 * r1.x; va.y += l1 * r1.y;
                        va.z += l1 * r1.z; va.w += l1 * r1.w;
                    }
                    if (s >= 3) {
                        float l2 = __ldcg(L2row + xx);
                        float4 r2 = __ldcg((const float4*)(R2row + yy));
                        va.x += l2 * r2.x; va.y += l2 * r2.y;
                        va.z += l2 * r2.z; va.w += l2 * r2.w;
                    }
                    sA[(kk + 0) * SSTR + lr] = va.x;
                    sA[(kk + 1) * SSTR + lr] = va.y;
                    sA[(kk + 2) * SSTR + lr] = va.z;
                    sA[(kk + 3) * SSTR + lr] = va.w;
                }
            }
            __syncthreads();

            // ---- GEMM: 64x64 x ck
            ull acc[4][2];
            #pragma unroll
            for (int i = 0; i < 4; i++) { acc[i][0] = 0ull; acc[i][1] = 0ull; }
            #pragma unroll 8
            for (int k = 0; k < ck; k++) {
                float4 av = *(const float4*)&sA[k * SSTR + x0];
                float4 bv = *(const float4*)&sB[k * SSTR + y0r];
                ull b01 = pack2(bv.x, bv.y), b23 = pack2(bv.z, bv.w);
                ull a2;
                a2 = pack2(av.x, av.x); fma2(acc[0][0], a2, b01); fma2(acc[0][1], a2, b23);
                a2 = pack2(av.y, av.y); fma2(acc[1][0], a2, b01); fma2(acc[1][1], a2, b23);
                a2 = pack2(av.z, av.z); fma2(acc[2][0], a2, b01); fma2(acc[2][1], a2, b23);
                a2 = pack2(av.w, av.w); fma2(acc[3][0], a2, b01); fma2(acc[3][1], a2, b23);
            }
            #pragma unroll
            for (int i = 0; i < 4; i++) {
                int row = tile * 64 + x0 + i;
                int base = modeB ? ((chunk << 8) + row) : ((chunk << 9) + row);
                float2 e0 = unpk(acc[i][0]), e1 = unpk(acc[i][1]);
                float4 o; o.x = e0.x; o.y = e0.y; o.z = e1.x; o.w = e1.y;
                *(float4*)&g_part[(size_t)base * Kk + y0r] = o;
            }
            __syncthreads();
            if (tid == 0) red_rel(&g_chunk_done[(s * 8 + tile) * CSTR], 1);

            // ---- fused deterministic reduction
            spin_ctr(&g_chunk_done[(s * 8 + tile) * CSTR], nch);
            if (modeB) {
                if (tid < 64 && chunk < R_t) {
                    int row = tile * 64 + chunk, a = tid;
                    float ssum = 0.f;
                    #pragma unroll 16
                    for (int cc = 0; cc < 64; cc++)
                        ssum += __ldcg(&g_part[(size_t)((cc << 8) + row) * Kk + a]);
                    int cell = row >> 3, b = row & 7;
                    g_chart[cidx(cell, cell + s, b, a)] = ssum;
                }
            } else {
                if (tid < 128) {
                    int rl = chunk * 2 + (tid >> 6);
                    if (rl < R_t) {
                        int row = tile * 64 + rl, a = tid & 63;
                        float ssum = 0.f;
                        #pragma unroll 16
                        for (int cc = 0; cc < 32; cc++)
                            ssum += __ldcg(&g_part[(size_t)((cc << 9) + row) * Kk + a]);
                        int cell = row >> 3, b = row & 7;
                        g_chart[cidx(cell, cell + s, b, a)] = ssum;
                    }
                }
            }
            __syncthreads();
            if (tid == 0) {
                int old = atom_ar(&g_red_tile[(s * 8 + tile) * CSTR], 1);
                if (old == nch - 1) {
                    int t = atom_ar(&g_tiles_done[s * CSTR], 1);
                    if (t == ntiles - 1) st_rel(&g_level_done, s);
                }
            }
        }

        // ---- A_pre(s+1): splits 2..s-1 into the other pair buffer
        if (s < Nn && s + 1 >= 4) {
            const int s2 = s + 1;
            const int rows2 = (Nn - s2 + 1) * Bb;
            float* const pairn = g_pair2[s2 & 1];
            for (int u = bid; u < rows2; u += nblk) {
                const int cell = u >> 3, b = u & 7;
                ull acc[4][2];
                #pragma unroll
                for (int i = 0; i < 4; i++) { acc[i][0] = 0ull; acc[i][1] = 0ull; }
                const float* Lbase = &g_chart[cidx(cell, cell, b, x0)];
                const float* Rbase = &g_chart[cidx(cell, cell + s2, b, y0r)];
                #pragma unroll 4
                for (int sp = 2; sp <= s2 - 2; sp++) {
                    float4 L = __ldcg((const float4*)(Lbase + (size_t)sp * (Bb * Kk)));
                    float4 R = __ldcg((const float4*)(Rbase + (size_t)sp * (NB1 * Bb * Kk)));
                    ull r01 = pack2(R.x, R.y), r23 = pack2(R.z, R.w);
                    ull l;
                    l = pack2(L.x, L.x); fma2(acc[0][0], l, r01); fma2(acc[0][1], l, r23);
                    l = pack2(L.y, L.y); fma2(acc[1][0], l, r01); fma2(acc[1][1], l, r23);
                    l = pack2(L.z, L.z); fma2(acc[2][0], l, r01); fma2(acc[2][1], l, r23);
                    l = pack2(L.w, L.w); fma2(acc[3][0], l, r01); fma2(acc[3][1], l, r23);
                }
                #pragma unroll
                for (int i = 0; i < 4; i++) {
                    float2 e0 = unpk(acc[i][0]), e1 = unpk(acc[i][1]);
                    float4 o; o.x = e0.x; o.y = e0.y; o.z = e1.x; o.w = e1.y;
                    *(float4*)&pairn[(size_t)u * KK2 + (x0 + i) * Kk + y0r] = o;
                }
                __syncthreads();
                if (tid == 0) red_rel(&g_pre_ready[(s2 * 8 + (u >> 6)) * CSTR], 1);
            }
        }
    }

    // ---- Final output
    if (bid == 0) {
        spin_level(Nn);
        if (w < Bb) {
            const int b = w;
            float p = 0.f;
            #pragma unroll
            for (int q = 0; q < 2; q++) {
                int a = lane + q * 32;
                p += prior[a] * __ldcg(&g_chart[cidx(0, Nn, b, a)]);
            }
            #pragma unroll
            for (int off = 16; off; off >>= 1) p += __shfl_down_sync(0xffffffffu, p, off);
            if (lane == 0) out[b] = p;
        }
    }

    // ---- End barrier + counter reset for next replay
    gbar(gen + 1, nblk);
    if (bid == 0) {
        for (int i = tid; i < NB1 * 8 * CSTR; i += 256) {
            g_pre_ready[i] = 0;
            g_chunk_done[i] = 0;
            g_red_tile[i] = 0;
        }
        for (int i = tid; i < NB1 * CSTR; i += 256) g_tiles_done[i] = 0;
        if (tid == 0) { g_cells0 = 0; g_level_done = 0; }
    }
}

extern "C" void kernel_launch(void* const* d_in, const int* in_sizes, int n_in,
                              void* d_out, int out_size)
{
    const float* seq   = (const float*)d_in[0];
    const float* rule  = (const float*)d_in[1];
    const float* emit  = (const float*)d_in[2];
    const float* prior = (const float*)d_in[3];
    float* out = (float*)d_out;

    cudaFuncSetAttribute(rbn_persistent, cudaFuncAttributeMaxDynamicSharedMemorySize, SMEM_BYTES);

    int dev = 0, nsm = 1;
    cudaGetDevice(&dev);
    cudaDeviceGetAttribute(&nsm, cudaDevAttrMultiProcessorCount, dev);
    int bpm = 1;
    cudaOccupancyMaxActiveBlocksPerMultiprocessor(&bpm, rbn_persistent, 256, SMEM_BYTES);
    if (bpm < 1) bpm = 1;
    if (bpm > 3) bpm = 3;
    int nblk = nsm * bpm;
    if (nblk > 444) nblk = 444;
    if (nblk < 256) nblk = 256;

    rbn_persistent<<<nblk, 256, SMEM_BYTES>>>(seq, rule, emit, prior, out, nblk);
}